// round 16
// baseline (speedup 1.0000x reference)
#include <cuda_runtime.h>
#include <cuda_bf16.h>
#include <cuda_fp16.h>
#include <cstdint>

#define IN_DIM   32
#define NB       11
#define FPAD     10                    // basis cols per feature in GEMM (sin/cos only)
#define HID      64
#define TILE_M   128
#define NCHUNK   4
#define FPC      8                     // features per chunk
#define KSTEPS   5                     // k16-steps per chunk (80 cols)
#define KS_TOTAL 20
#define THREADS  256
#define NCTAS    296                   // 148 SMs x 2 resident CTAs

#define A_STRIDE_B  176                // bytes per A row (88 halves; 80 used)

// ---- SMEM layout (bytes) ----
#define ABUF_BYTES  (TILE_M * A_STRIDE_B)       // 22528
#define SMEM_B      (2 * ABUF_BYTES)            // 45056
#define BFRAG_BYTES (KS_TOTAL * 8 * 32 * 8)     // 40960
#define SMEM_C0     (SMEM_B + BFRAG_BYTES)      // 86016
#define SMEM_TOTAL  (SMEM_C0 + 256)             // 86272 -> 2 CTAs/SM

// ---------------------------------------------------------------- helpers
__device__ __forceinline__ uint32_t smem_u32(const void* p) {
    uint32_t a;
    asm("{ .reg .u64 t; cvta.to.shared.u64 t, %1; cvt.u32.u64 %0, t; }"
        : "=r"(a) : "l"(p));
    return a;
}
__device__ __forceinline__ void ldm4(uint32_t* r, uint32_t a) {
    asm volatile("ldmatrix.sync.aligned.m8n8.x4.shared.b16 {%0,%1,%2,%3}, [%4];"
                 : "=r"(r[0]), "=r"(r[1]), "=r"(r[2]), "=r"(r[3]) : "r"(a));
}
__device__ __forceinline__ void sts64(uint32_t a, uint32_t v0, uint32_t v1) {
    asm volatile("st.shared.v2.b32 [%0], {%1, %2};" :: "r"(a), "r"(v0), "r"(v1) : "memory");
}
__device__ __forceinline__ void lds64(uint32_t* r, uint32_t a) {
    asm volatile("ld.shared.v2.b32 {%0,%1}, [%2];"
                 : "=r"(r[0]), "=r"(r[1]) : "r"(a));
}
__device__ __forceinline__ void mma16816(float* d, const uint32_t* a, const uint32_t* b) {
    asm volatile(
        "mma.sync.aligned.m16n8k16.row.col.f32.f16.f16.f32 "
        "{%0,%1,%2,%3}, {%4,%5,%6,%7}, {%8,%9}, {%0,%1,%2,%3};"
        : "+f"(d[0]), "+f"(d[1]), "+f"(d[2]), "+f"(d[3])
        : "r"(a[0]), "r"(a[1]), "r"(a[2]), "r"(a[3]), "r"(b[0]), "r"(b[1]));
}

// sin/cos harmonics 1..5 of xv (MUFU + product recurrence)
__device__ __forceinline__ void sincos_harm(float xv, float* v) {
    float s1, c1;
    __sincosf(xv, &s1, &c1);
    float s2 = 2.f * s1 * c1;
    float c2 = fmaf(c1, c1, -(s1 * s1));
    float s3 = s2 * c1 + c2 * s1;
    float c3 = c2 * c1 - s2 * s1;
    float s4 = s3 * c1 + c3 * s1;
    float c4 = c3 * c1 - s3 * s1;
    float s5 = s4 * c1 + c4 * s1;
    float c5 = c4 * c1 - s4 * s1;
    v[0] = s1; v[1] = c1; v[2] = s2; v[3] = c2; v[4] = s3;
    v[5] = c3; v[6] = s4; v[7] = c4; v[8] = s5; v[9] = c5;
}

// ---------------------------------------------------------------- A generation
// 512 jobs: 128 rows x 4 feature-pairs; each job 2 sincos + 5 STS.64
__device__ __forceinline__ void gen_chunk(const float* __restrict__ x,
                                          uint32_t sbase, long row0, int n_rows,
                                          int ch, int buf, int tid)
{
    const uint32_t hoff = sbase + buf * ABUF_BYTES;
    #pragma unroll
    for (int i = 0; i < 2; i++) {
        const int job = tid + THREADS * i;     // 0..511
        const int r   = job >> 2;
        const int fp  = job & 3;
        const long grow = row0 + r;
        const int f0 = ch * FPC + fp * 2;

        float2 xv2 = make_float2(0.f, 0.f);
        if (grow < n_rows)
            xv2 = __ldg((const float2*)(x + grow * IN_DIM + f0));

        float v[20];
        sincos_harm(xv2.x, v);
        sincos_harm(xv2.y, v + 10);

        const uint32_t wb = hoff + r * A_STRIDE_B + fp * 40;
        #pragma unroll
        for (int p = 0; p < 5; p++) {
            __half2 a = __floats2half2_rn(v[4 * p + 0], v[4 * p + 1]);
            __half2 b = __floats2half2_rn(v[4 * p + 2], v[4 * p + 3]);
            sts64(wb + p * 8, *(uint32_t*)&a, *(uint32_t*)&b);
        }
    }
}

// ---------------------------------------------------------------- main kernel
__global__ void __launch_bounds__(THREADS, 2)
kan_mma_kernel(const float* __restrict__ x, const float* __restrict__ W,
               const float* __restrict__ bias, float* __restrict__ out,
               int n_rows, int ntiles)
{
    extern __shared__ __align__(16) unsigned char smem[];
    const uint32_t sbase = smem_u32(smem);
    const int tid  = threadIdx.x;
    const int lane = tid & 31;
    const int wid  = tid >> 5;
    const int mw   = wid & 3;    // M warp: rows mw*32
    const int nw   = wid >> 2;   // N warp: cols nw*32

    // ============ one-time: build B fragments + c0 in SMEM from W ============
    // iteration i builds k-step group ksg=i (256 entries of 8B).
    // entry: lane t, n-tile nt=wid, n = nt*8 + t/4, kbase = i*16 + (t%4)*2.
    {
        const int n     = wid * 8 + (lane >> 2);
        const int kloc  = (lane & 3) * 2;
        #pragma unroll
        for (int i = 0; i < KS_TOTAL; i++) {
            const int kbase = i * 16 + kloc;
            uint32_t hi[2];
            #pragma unroll
            for (int half = 0; half < 2; half++) {
                int k0 = kbase + half * 8;
                int k1 = k0 + 1;
                float v0 = W[((k0 / FPAD) * NB + (k0 % FPAD) + 1) * HID + n];
                float v1 = W[((k1 / FPAD) * NB + (k1 % FPAD) + 1) * HID + n];
                __half2 h2 = __floats2half2_rn(v0, v1);
                hi[half] = *(uint32_t*)&h2;
            }
            const uint32_t off = sbase + SMEM_B + (uint32_t)(tid + 256 * i) * 8;
            sts64(off, hi[0], hi[1]);
        }
        if (tid < HID) {
            float s = 0.f;
            #pragma unroll
            for (int f = 0; f < IN_DIM; f++)
                s += W[(f * NB) * HID + tid] + bias[f * HID + tid];
            asm volatile("st.shared.f32 [%0], %1;"
                         :: "r"(sbase + SMEM_C0 + tid * 4), "f"(s) : "memory");
        }
    }

    const int lrow = lane & 15, lcol = lane >> 4;
    const uint32_t aOff = (uint32_t)(mw * 32 + lrow) * A_STRIDE_B + lcol * 16;
    const uint32_t bBase = sbase + SMEM_B + (uint32_t)(nw * 4) * 256 + lane * 8;

    int buf = 0;
    if (blockIdx.x < (unsigned)ntiles)
        gen_chunk(x, sbase, (long)blockIdx.x * TILE_M, n_rows, 0, 0, tid);
    __syncthreads();   // B + c0 + first A chunk ready

    for (int tile = blockIdx.x; tile < ntiles; tile += gridDim.x) {
        const long tile_row0 = (long)tile * TILE_M;

        float d[2][4][4];
        #pragma unroll
        for (int mt = 0; mt < 2; mt++)
            #pragma unroll
            for (int j = 0; j < 4; j++)
                #pragma unroll
                for (int e = 0; e < 4; e++) d[mt][j][e] = 0.f;

        for (int ch = 0; ch < NCHUNK; ch++) {
            // produce next chunk (next tile's chunk 0 when wrapping)
            const int  ntile = (ch < NCHUNK - 1) ? tile : tile + gridDim.x;
            const int  nch   = (ch < NCHUNK - 1) ? ch + 1 : 0;
            if (ntile < ntiles)
                gen_chunk(x, sbase, (long)ntile * TILE_M, n_rows, nch, buf ^ 1, tid);

            // === mma on current buffer: 5 k-steps, all operands in SMEM ===
            const uint32_t aBase = sbase + buf * ABUF_BYTES + aOff;
            #pragma unroll
            for (int s = 0; s < KSTEPS; s++) {
                uint32_t aAddr = aBase + s * 32;
                uint32_t ah[2][4];
                ldm4(ah[0], aAddr);
                ldm4(ah[1], aAddr + 16 * A_STRIDE_B);

                // B fragments: conflict-free LDS.64 (256B contiguous per fragment)
                const uint32_t bk = bBase + (uint32_t)(ch * KSTEPS + s) * 2048;
                uint32_t bh[4][2];
                #pragma unroll
                for (int j = 0; j < 4; j++)
                    lds64(bh[j], bk + (uint32_t)j * 256);

                #pragma unroll
                for (int mt = 0; mt < 2; mt++)
                    #pragma unroll
                    for (int j = 0; j < 4; j++)
                        mma16816(d[mt][j], ah[mt], bh[j]);
            }
            __syncthreads();
            buf ^= 1;
        }

        // ---- epilogue: add fp32 constant from SMEM c0, store ----
        #pragma unroll
        for (int mt = 0; mt < 2; mt++) {
            #pragma unroll
            for (int half = 0; half < 2; half++) {
                const long grow = tile_row0 + mw * 32 + mt * 16 + (lane >> 2) + half * 8;
                if (grow < n_rows) {
                    #pragma unroll
                    for (int j = 0; j < 4; j++) {
                        const int col = nw * 32 + j * 8 + (lane & 3) * 2;
                        float c0, c1v;
                        asm volatile("ld.shared.f32 %0, [%1];"
                                     : "=f"(c0) : "r"(sbase + SMEM_C0 + col * 4));
                        asm volatile("ld.shared.f32 %0, [%1];"
                                     : "=f"(c1v) : "r"(sbase + SMEM_C0 + (col + 1) * 4));
                        float2 v;
                        v.x = d[mt][j][half * 2 + 0] + c0;
                        v.y = d[mt][j][half * 2 + 1] + c1v;
                        *(float2*)(out + grow * HID + col) = v;
                    }
                }
            }
        }
    }
}

// ---------------------------------------------------------------- launch
extern "C" void kernel_launch(void* const* d_in, const int* in_sizes, int n_in,
                              void* d_out, int out_size)
{
    const float* x = (const float*)d_in[0];
    const float* W = (const float*)d_in[1];
    const float* b = (const float*)d_in[2];
    float* out = (float*)d_out;

    const int n_rows = in_sizes[0] / IN_DIM;    // 131072
    const int ntiles = (n_rows + TILE_M - 1) / TILE_M;
    const int grid = ntiles < NCTAS ? ntiles : NCTAS;

    cudaFuncSetAttribute(kan_mma_kernel,
                         cudaFuncAttributeMaxDynamicSharedMemorySize, SMEM_TOTAL);

    kan_mma_kernel<<<grid, THREADS, SMEM_TOTAL>>>(x, W, b, out, n_rows, ntiles);
}